// round 9
// baseline (speedup 1.0000x reference)
#include <cuda_runtime.h>
#include <cstdint>

// SpiralConv gather-GEMM, mma.sync TF32. R9 = R8 with the cp.async.mbarrier
// .noinc fix: 4 warps/CTA, 64x64 warp tiles, 3-stage mbarrier pipeline,
// no __syncthreads in the mainloop (warps free-run).
// out[m,o] = relu(sum_k A[m,k]*W[o,k] + b[o]) * zp[m%N]; M=96000, K=2048, N=128.

constexpr int Bq = 8, Nq = 12000, Fq = 128, Sq = 16, OUTq = 128;
constexpr int Kq = Sq * Fq;       // 2048
constexpr int Mtot = Bq * Nq;     // 96000
constexpr int BM = 128;
constexpr int NITER = Kq / 32;    // 64 (BK=32)
constexpr int NST = 3;

// Pre-rounded (TF32-RNE), per-32-group permuted copies:
// slot s (float4) of each 32-float group holds k = {(s&3)+16*(s>>2)} + 4j.
__device__ float g_x[Bq * Nq * Fq];
__device__ float g_w[OUTq * Kq];

constexpr int STG = BM * 128;                       // 16384 per tile stage
constexpr int OFF_A = 0;                            // 3 stages A
constexpr int OFF_B = OFF_A + NST * STG;            // 49152, 3 stages B
constexpr int OFF_ATAB = OFF_B + NST * STG;         // 98304 (128*16 uint32)
constexpr int OFF_BIAS = OFF_ATAB + BM * Sq * 4;    // 106496
constexpr int OFF_MBAR = OFF_BIAS + OUTq * 4;       // 107008 (3 x {full,empty})
constexpr int SMEM_BYTES = OFF_MBAR + NST * 16;     // 107056

__device__ __forceinline__ float tf32_rne(float f) {
    uint32_t u;
    asm("cvt.rna.tf32.f32 %0, %1;" : "=r"(u) : "f"(f));
    return __uint_as_float(u);
}

__device__ __forceinline__ void cp_async16(void* sdst, const void* gsrc) {
    unsigned d = (unsigned)__cvta_generic_to_shared(sdst);
    asm volatile("cp.async.cg.shared.global [%0], [%1], 16;" :: "r"(d), "l"(gsrc));
}

__device__ __forceinline__ void mbar_init(uint32_t a, uint32_t cnt) {
    asm volatile("mbarrier.init.shared.b64 [%0], %1;" :: "r"(a), "r"(cnt) : "memory");
}

__device__ __forceinline__ void mbar_arrive(uint32_t a) {
    asm volatile("mbarrier.arrive.shared::cta.b64 _, [%0];" :: "r"(a) : "memory");
}

__device__ __forceinline__ void cpasync_mbar_arrive_noinc(uint32_t a) {
    asm volatile("cp.async.mbarrier.arrive.noinc.shared::cta.b64 [%0];" :: "r"(a) : "memory");
}

__device__ __forceinline__ void mbar_wait(uint32_t a, uint32_t parity) {
    uint32_t done;
    asm volatile("{\n\t.reg .pred p;\n\t"
                 "mbarrier.try_wait.parity.acquire.cta.shared::cta.b64 p, [%1], %2;\n\t"
                 "selp.b32 %0, 1, 0, p;\n\t}"
                 : "=r"(done) : "r"(a), "r"(parity) : "memory");
    if (!done) {
        asm volatile("{\n\t.reg .pred P1;\n\t"
                     "W_%=:\n\t"
                     "mbarrier.try_wait.parity.acquire.cta.shared::cta.b64 P1, [%0], %1, 0x989680;\n\t"
                     "@P1 bra.uni D_%=;\n\t"
                     "bra.uni W_%=;\n\t"
                     "D_%=:\n\t}"
                     :: "r"(a), "r"(parity) : "memory");
    }
}

// ---- prepass: TF32-RNE round + per-32-group fragment permutation ----
__global__ void prep_kernel(const float* __restrict__ x, const float* __restrict__ W,
                            int xn4, int tot4) {
    int t = blockIdx.x * 256 + threadIdx.x;
    if (t >= tot4) return;
    const float* src;
    float* dst;
    int w4 = t;
    if (t < xn4) { src = x; dst = g_x; }
    else         { src = W; dst = g_w; w4 = t - xn4; }
    int w0 = w4 * 4;
    int s = (w0 >> 2) & 7;
    int c0 = (s & 3) + ((s >> 2) << 4);
    int gb = (w0 & ~31) + c0;
    float4 v;
    v.x = tf32_rne(src[gb]);
    v.y = tf32_rne(src[gb + 4]);
    v.z = tf32_rne(src[gb + 8]);
    v.w = tf32_rne(src[gb + 12]);
    reinterpret_cast<float4*>(dst)[w4] = v;
}

extern __shared__ char smem[];

__global__ __launch_bounds__(128, 2) void spiral_mma_kernel(
    const float* __restrict__ bias,
    const int*   __restrict__ adj,
    const float* __restrict__ zp,
    float*       __restrict__ out)
{
    const int tid = threadIdx.x;
    const int m0 = blockIdx.x * BM;
    uint32_t sb;
    asm("{ .reg .u64 t; cvta.to.shared.u64 t, %1; cvt.u32.u64 %0, t; }"
        : "=r"(sb) : "l"(smem));

    uint32_t* atab  = reinterpret_cast<uint32_t*>(smem + OFF_ATAB);
    float*    sbias = reinterpret_cast<float*>(smem + OFF_BIAS);

    for (int i = tid; i < BM * Sq; i += 128) {
        int r = i >> 4, s = i & 15;
        int mm = m0 + r;
        int b = mm / Nq, n = mm - b * Nq;
        atab[i] = (uint32_t)(b * Nq + adj[n * Sq + s]) << 9;
    }
    sbias[tid] = bias[tid];
    if (tid == 0) {
        #pragma unroll
        for (int s = 0; s < NST; ++s) {
            mbar_init(sb + OFF_MBAR + s * 16, 128);      // full[s]
            mbar_init(sb + OFF_MBAR + s * 16 + 8, 128);  // empty[s]
        }
    }
    __syncthreads();

    // loader geometry: thread covers rows lr+16j (j=0..7), chunk slot lc
    const int lr = tid >> 3;
    const int lc = tid & 7;
    const uint32_t* atp = atab + lr * 16;
    int adst[8];
    const char* wsrc[8];
    #pragma unroll
    for (int j = 0; j < 8; ++j) {
        int row = lr + j * 16;
        adst[j] = row * 128 + ((lc ^ ((row & 1) << 2)) << 4);
        wsrc[j] = reinterpret_cast<const char*>(g_w) + row * (Kq * 4) + lc * 16;
    }

    auto produce = [&](int st, int parity, int it2) {
        mbar_wait(sb + OFF_MBAR + st * 16 + 8, parity);       // empty[st]
        const int sidx = it2 >> 2;
        const char* gx = reinterpret_cast<const char*>(g_x) + ((it2 & 3) << 7) + lc * 16;
        const int wadv = it2 << 7;
        char* abase = smem + OFF_A + st * STG;
        char* bbase = smem + OFF_B + st * STG;
        #pragma unroll
        for (int j = 0; j < 8; ++j)
            cp_async16(abase + adst[j], gx + atp[256 * j + sidx]);
        #pragma unroll
        for (int j = 0; j < 8; ++j)
            cp_async16(bbase + adst[j], wsrc[j] + wadv);
        cpasync_mbar_arrive_noinc(sb + OFF_MBAR + st * 16);   // full[st] on completion
    };

    const int lane = tid & 31;
    const int warp = tid >> 5;
    const int wm = (warp & 1) * 64;   // 2 warps over M
    const int wn = (warp >> 1) * 64;  // 2 warps over N
    const int tr = lane >> 2;
    const int tc = lane & 3;
    const int swz = (tr & 1) << 2;
    const int chunk0 = tc ^ swz;
    const int chunk1 = (tc + 4) ^ swz;

    float acc[4][8][4];
    #pragma unroll
    for (int a = 0; a < 4; ++a)
        #pragma unroll
        for (int b2 = 0; b2 < 8; ++b2)
            #pragma unroll
            for (int c = 0; c < 4; ++c) acc[a][b2][c] = 0.f;

    auto consume = [&](int st, int parity) {
        mbar_wait(sb + OFF_MBAR + st * 16, parity);           // full[st]
        const float4* A4 = reinterpret_cast<const float4*>(smem + OFF_A + st * STG);
        const float4* B4 = reinterpret_cast<const float4*>(smem + OFF_B + st * STG);
        #pragma unroll
        for (int h = 0; h < 2; ++h) {
            const int chunk = h ? chunk1 : chunk0;
            float4 bfr[8];
            #pragma unroll
            for (int nt = 0; nt < 8; ++nt)
                bfr[nt] = B4[(wn + nt * 8 + tr) * 8 + chunk];
            #pragma unroll
            for (int mt = 0; mt < 4; ++mt) {
                const int r = wm + mt * 16 + tr;
                float4 alo = A4[r * 8 + chunk];
                float4 ahi = A4[(r + 8) * 8 + chunk];
                uint32_t a0 = __float_as_uint(alo.x), a1 = __float_as_uint(ahi.x);
                uint32_t a2 = __float_as_uint(alo.y), a3 = __float_as_uint(ahi.y);
                #pragma unroll
                for (int nt = 0; nt < 8; ++nt)
                    asm volatile(
                        "mma.sync.aligned.m16n8k8.row.col.f32.tf32.tf32.f32 "
                        "{%0,%1,%2,%3}, {%4,%5,%6,%7}, {%8,%9}, {%0,%1,%2,%3};"
                        : "+f"(acc[mt][nt][0]), "+f"(acc[mt][nt][1]),
                          "+f"(acc[mt][nt][2]), "+f"(acc[mt][nt][3])
                        : "r"(a0), "r"(a1), "r"(a2), "r"(a3),
                          "r"(__float_as_uint(bfr[nt].x)), "r"(__float_as_uint(bfr[nt].y)));
                uint32_t c0 = __float_as_uint(alo.z), c1 = __float_as_uint(ahi.z);
                uint32_t c2 = __float_as_uint(alo.w), c3 = __float_as_uint(ahi.w);
                #pragma unroll
                for (int nt = 0; nt < 8; ++nt)
                    asm volatile(
                        "mma.sync.aligned.m16n8k8.row.col.f32.tf32.tf32.f32 "
                        "{%0,%1,%2,%3}, {%4,%5,%6,%7}, {%8,%9}, {%0,%1,%2,%3};"
                        : "+f"(acc[mt][nt][0]), "+f"(acc[mt][nt][1]),
                          "+f"(acc[mt][nt][2]), "+f"(acc[mt][nt][3])
                        : "r"(c0), "r"(c1), "r"(c2), "r"(c3),
                          "r"(__float_as_uint(bfr[nt].z)), "r"(__float_as_uint(bfr[nt].w)));
            }
        }
        mbar_arrive(sb + OFF_MBAR + st * 16 + 8);             // empty[st]
    };

    // prologue: stages 0,1 (fresh-barrier empty-waits pass with parity 1)
    produce(0, 1, 0);
    produce(1, 1, 1);

    int ps = 2, pp = 1;   // producer stage/phase
    int cs = 0, cp = 0;   // consumer stage/phase
    #pragma unroll 1
    for (int it = 0; it < NITER; ++it) {
        if (it + 2 < NITER) {
            produce(ps, pp, it + 2);
            if (++ps == NST) { ps = 0; pp ^= 1; }
        }
        consume(cs, cp);
        if (++cs == NST) { cs = 0; cp ^= 1; }
    }

    // ---- epilogue: bias + relu + zero_padding ----
    #pragma unroll
    for (int mt = 0; mt < 4; ++mt) {
        #pragma unroll
        for (int hh = 0; hh < 2; ++hh) {
            int m = m0 + wm + mt * 16 + hh * 8 + tr;
            float z = zp[m % Nq];
            float* orow = out + (long)m * OUTq;
            #pragma unroll
            for (int nt = 0; nt < 8; ++nt) {
                int o = wn + nt * 8 + 2 * tc;
                float v0 = fmaxf(acc[mt][nt][hh * 2 + 0] + sbias[o], 0.f) * z;
                float v1 = fmaxf(acc[mt][nt][hh * 2 + 1] + sbias[o + 1], 0.f) * z;
                *reinterpret_cast<float2*>(orow + o) = make_float2(v0, v1);
            }
        }
    }
}

extern "C" void kernel_launch(void* const* d_in, const int* in_sizes, int n_in,
                              void* d_out, int out_size) {
    const float* x    = (const float*)d_in[0];
    const float* W    = (const float*)d_in[1];
    const float* bias = (const float*)d_in[2];
    const int*   adj  = (const int*)d_in[3];
    const float* zp   = (const float*)d_in[4];
    float* out = (float*)d_out;

    int xn4 = (Bq * Nq * Fq) / 4;
    int tot4 = xn4 + (OUTq * Kq) / 4;
    prep_kernel<<<(tot4 + 255) / 256, 256>>>(x, W, xn4, tot4);

    cudaFuncSetAttribute(spiral_mma_kernel,
                         cudaFuncAttributeMaxDynamicSharedMemorySize, SMEM_BYTES);
    spiral_mma_kernel<<<Mtot / BM, 128, SMEM_BYTES>>>(bias, adj, zp, out);
}

// round 10
// speedup vs baseline: 1.7169x; 1.7169x over previous
#include <cuda_runtime.h>
#include <cuda_fp16.h>
#include <cstdint>

// SpiralConv gather-GEMM. R10: FP16 m16n8k16 mma.sync (2x legacy-HMMA rate vs
// tf32; same 10-bit mantissa -> same accuracy), fragment-native gmem layout,
// conflict-free LDS.128, 3-stage cp.async pipeline, R5 skeleton.
// out[m,o] = relu(sum_k A[m,k]*W[o,k] + b[o]) * zp[m%N]; M=96000, K=2048, N=128.

constexpr int Bq = 8, Nq = 12000, Fq = 128, Sq = 16, OUTq = 128;
constexpr int Kq = Sq * Fq;       // 2048
constexpr int Mtot = Bq * Nq;     // 96000
constexpr int BM = 128;
constexpr int NITER = Kq / 32;    // 64 (BK=32)
constexpr int NST = 3;

// fp16 copies, per-32-group permuted: 16B slot s of each 32-elem group holds
// k = {2s,2s+1, 2s+8,2s+9, 2s+16,2s+17, 2s+24,2s+25}.
__device__ __half g_x[Bq * Nq * Fq];
__device__ __half g_w[OUTq * Kq];

// smem layout (bytes). A/B stage rows are 64B (4 x 16B chunks).
constexpr int STG = BM * 64;                        // 8192 per tile stage
constexpr int OFF_A = 0;                            // 3 stages
constexpr int OFF_B = OFF_A + NST * STG;            // 24576
constexpr int OFF_ATAB = OFF_B + NST * STG;         // 49152 (128*16 uint32)
constexpr int OFF_BIAS = OFF_ATAB + BM * Sq * 4;    // 57344
constexpr int SMEM_BYTES = OFF_BIAS + OUTq * 4;     // 57856

__device__ __forceinline__ void cp_async16(void* sdst, const void* gsrc) {
    unsigned d = (unsigned)__cvta_generic_to_shared(sdst);
    asm volatile("cp.async.cg.shared.global [%0], [%1], 16;" :: "r"(d), "l"(gsrc));
}

// ---- prepass: fp32 -> fp16 with per-32-group fragment permutation ----
__global__ void prep_kernel(const float* __restrict__ x, const float* __restrict__ W,
                            int xch, int totch) {
    int t = blockIdx.x * 256 + threadIdx.x;
    if (t >= totch) return;
    const float* src;
    __half* dst;
    int ch = t;
    if (t < xch) { src = x; dst = g_x; }
    else         { src = W; dst = g_w; ch = t - xch; }
    int gb = (ch >> 2) * 32 + (ch & 3) * 2;
    __half2 h0 = __float22half2_rn(*reinterpret_cast<const float2*>(src + gb));
    __half2 h1 = __float22half2_rn(*reinterpret_cast<const float2*>(src + gb + 8));
    __half2 h2 = __float22half2_rn(*reinterpret_cast<const float2*>(src + gb + 16));
    __half2 h3 = __float22half2_rn(*reinterpret_cast<const float2*>(src + gb + 24));
    uint4 v;
    v.x = *reinterpret_cast<uint32_t*>(&h0);
    v.y = *reinterpret_cast<uint32_t*>(&h1);
    v.z = *reinterpret_cast<uint32_t*>(&h2);
    v.w = *reinterpret_cast<uint32_t*>(&h3);
    reinterpret_cast<uint4*>(dst)[ch] = v;
}

extern __shared__ char smem[];

__global__ __launch_bounds__(256, 2) void spiral_mma_kernel(
    const float* __restrict__ bias,
    const int*   __restrict__ adj,
    const float* __restrict__ zp,
    float*       __restrict__ out)
{
    const int tid = threadIdx.x;
    const int m0 = blockIdx.x * BM;

    uint32_t* atab  = reinterpret_cast<uint32_t*>(smem + OFF_ATAB);
    float*    sbias = reinterpret_cast<float*>(smem + OFF_BIAS);

    // gather table: byte offset of fp16 x-row (256B each)
    for (int i = tid; i < BM * Sq; i += 256) {
        int r = i >> 4, s = i & 15;
        int mm = m0 + r;
        int b = mm / Nq, n = mm - b * Nq;
        atab[i] = (uint32_t)(b * Nq + adj[n * Sq + s]) << 8;
    }
    if (tid < OUTq) sbias[tid] = bias[tid];
    __syncthreads();

    // loader: thread covers rows lr, lr+64; 16B chunk slot lc
    const int lr = tid >> 2;          // 0..63
    const int lc = tid & 3;
    const uint32_t* atp = atab + lr * 16;   // row lr; row lr+64 -> +64*16
    int adst[2];
    const char* wsrc[2];
    #pragma unroll
    for (int j = 0; j < 2; ++j) {
        int row = lr + j * 64;
        adst[j] = row * 64 + ((lc ^ ((row >> 1) & 3)) << 4);
        wsrc[j] = reinterpret_cast<const char*>(g_w) + row * (Kq * 2) + lc * 16;
    }

    auto load_stage = [&](int st, int it2) {
        const int sidx = it2 >> 2;
        const char* gx = reinterpret_cast<const char*>(g_x) + ((it2 & 3) << 6) + lc * 16;
        const int wadv = it2 << 6;          // 64B of W per iter
        char* abase = smem + OFF_A + st * STG;
        char* bbase = smem + OFF_B + st * STG;
        #pragma unroll
        for (int j = 0; j < 2; ++j)
            cp_async16(abase + adst[j], gx + atp[1024 * j + sidx]);
        #pragma unroll
        for (int j = 0; j < 2; ++j)
            cp_async16(bbase + adst[j], wsrc[j] + wadv);
    };

    load_stage(0, 0); asm volatile("cp.async.commit_group;");
    load_stage(1, 1); asm volatile("cp.async.commit_group;");

    const int lane = tid & 31;
    const int warp = tid >> 5;
    const int wm = (warp & 1) * 64;   // 2 warps over M
    const int wn = (warp >> 1) * 32;  // 4 warps over N
    const int tr = lane >> 2;         // 0..7
    const int tc = lane & 3;          // 0..3
    const int chn = tc ^ (tr >> 1);   // conflict-free chunk slot (per-thread const)

    float acc[4][4][4];
    #pragma unroll
    for (int a = 0; a < 4; ++a)
        #pragma unroll
        for (int b2 = 0; b2 < 4; ++b2)
            #pragma unroll
            for (int c = 0; c < 4; ++c) acc[a][b2][c] = 0.f;

    int cur = 0, nx2 = 2;
    #pragma unroll 1
    for (int it = 0; it < NITER; ++it) {
        asm volatile("cp.async.wait_group 1;");
        __syncthreads();
        if (it + 2 < NITER) load_stage(nx2, it + 2);
        asm volatile("cp.async.commit_group;");

        const uint4* A4 = reinterpret_cast<const uint4*>(smem + OFF_A + cur * STG);
        const uint4* B4 = reinterpret_cast<const uint4*>(smem + OFF_B + cur * STG);

        uint4 bfr[4];
        #pragma unroll
        for (int nt = 0; nt < 4; ++nt)
            bfr[nt] = B4[(wn + nt * 8 + tr) * 4 + chn];

        #pragma unroll
        for (int mt = 0; mt < 4; ++mt) {
            const int r = wm + mt * 16 + tr;
            uint4 alo = A4[r * 4 + chn];
            uint4 ahi = A4[(r + 8) * 4 + chn];
            // k-step 0 (k 0..15 of this 32-block)
            #pragma unroll
            for (int nt = 0; nt < 4; ++nt)
                asm volatile(
                    "mma.sync.aligned.m16n8k16.row.col.f32.f16.f16.f32 "
                    "{%0,%1,%2,%3}, {%4,%5,%6,%7}, {%8,%9}, {%0,%1,%2,%3};"
                    : "+f"(acc[mt][nt][0]), "+f"(acc[mt][nt][1]),
                      "+f"(acc[mt][nt][2]), "+f"(acc[mt][nt][3])
                    : "r"(alo.x), "r"(ahi.x), "r"(alo.y), "r"(ahi.y),
                      "r"(bfr[nt].x), "r"(bfr[nt].y));
            // k-step 1 (k 16..31)
            #pragma unroll
            for (int nt = 0; nt < 4; ++nt)
                asm volatile(
                    "mma.sync.aligned.m16n8k16.row.col.f32.f16.f16.f32 "
                    "{%0,%1,%2,%3}, {%4,%5,%6,%7}, {%8,%9}, {%0,%1,%2,%3};"
                    : "+f"(acc[mt][nt][0]), "+f"(acc[mt][nt][1]),
                      "+f"(acc[mt][nt][2]), "+f"(acc[mt][nt][3])
                    : "r"(alo.z), "r"(ahi.z), "r"(alo.w), "r"(ahi.w),
                      "r"(bfr[nt].z), "r"(bfr[nt].w));
        }

        cur = (cur == NST - 1) ? 0 : cur + 1;
        nx2 = (nx2 == NST - 1) ? 0 : nx2 + 1;
    }

    // ---- epilogue: bias + relu + zero_padding ----
    #pragma unroll
    for (int mt = 0; mt < 4; ++mt) {
        #pragma unroll
        for (int hh = 0; hh < 2; ++hh) {
            int m = m0 + wm + mt * 16 + hh * 8 + tr;
            float z = zp[m % Nq];
            float* orow = out + (long)m * OUTq;
            #pragma unroll
            for (int nt = 0; nt < 4; ++nt) {
                int o = wn + nt * 8 + 2 * tc;
                float v0 = fmaxf(acc[mt][nt][hh * 2 + 0] + sbias[o], 0.f) * z;
                float v1 = fmaxf(acc[mt][nt][hh * 2 + 1] + sbias[o + 1], 0.f) * z;
                *reinterpret_cast<float2*>(orow + o) = make_float2(v0, v1);
            }
        }
    }
}

extern "C" void kernel_launch(void* const* d_in, const int* in_sizes, int n_in,
                              void* d_out, int out_size) {
    const float* x    = (const float*)d_in[0];
    const float* W    = (const float*)d_in[1];
    const float* bias = (const float*)d_in[2];
    const int*   adj  = (const int*)d_in[3];
    const float* zp   = (const float*)d_in[4];
    float* out = (float*)d_out;

    int xch = (Bq * Nq * Fq) / 8;            // 1,536,000 16B chunks
    int totch = xch + (OUTq * Kq) / 8;       // + 32,768
    prep_kernel<<<(totch + 255) / 256, 256>>>(x, W, xch, totch);

    cudaFuncSetAttribute(spiral_mma_kernel,
                         cudaFuncAttributeMaxDynamicSharedMemorySize, SMEM_BYTES);
    spiral_mma_kernel<<<Mtot / BM, 256, SMEM_BYTES>>>(bias, adj, zp, out);
}